// round 14
// baseline (speedup 1.0000x reference)
#include <cuda_runtime.h>
#include <cstdint>

typedef unsigned long long u64;

#define NQ 16384
#define NB 128
#define NF 64
#define HD 128
#define EPSF 1e-8f

#define THREADS 768
#define WARPS_PER_CTA 24
#define PAIRS_PER_CTA 12
#define MAXQ 9

// prep outputs. Pair p couples b=p and b=p+64.
// g_probeA[f*64+p] = {P_real[p], P_real[p+64], P_imag[p], P_imag[p+64]} (16B)
// g_probeW[(f*64+p)*2 + {0,1}] = {w_p, w_p+64}                          (8B)
// g_probeMW[(f*64+p)*2 + {0,1}] = {mw_p, mw_p+64}                       (8B)
__device__ float g_probeA[NF * 64 * 4];
__device__ float g_probeW[NF * 64 * 2];
__device__ float g_probeMW[NF * 64 * 2];

// ---------- f32x2 helpers ----------
__device__ __forceinline__ u64 f2pk(float lo, float hi) {
    u64 r; asm("mov.b64 %0, {%1,%2};" : "=l"(r) : "f"(lo), "f"(hi)); return r;
}
__device__ __forceinline__ void f2upk(float& lo, float& hi, u64 v) {
    asm("mov.b64 {%0,%1}, %2;" : "=f"(lo), "=f"(hi) : "l"(v));
}
__device__ __forceinline__ u64 f2add(u64 a, u64 b) {
    u64 d; asm("add.rn.f32x2 %0, %1, %2;" : "=l"(d) : "l"(a), "l"(b)); return d;
}
__device__ __forceinline__ u64 f2fma(u64 a, u64 b, u64 c) {
    u64 d; asm("fma.rn.f32x2 %0, %1, %2, %3;" : "=l"(d) : "l"(a), "l"(b), "l"(c)); return d;
}
__device__ __forceinline__ float sqrt_apx(float x) {
    float r; asm("sqrt.approx.f32 %0, %1;" : "=f"(r) : "f"(x)); return r;
}
__device__ __forceinline__ float rcp_apx(float x) {
    float r; asm("rcp.approx.f32 %0, %1;" : "=f"(r) : "f"(x)); return r;
}
__device__ __forceinline__ uint32_t su32(const void* p) {
    uint32_t a;
    asm("{ .reg .u64 t; cvta.to.shared.u64 t, %1; cvt.u32.u64 %0, t; }"
        : "=r"(a) : "l"(p));
    return a;
}

// ---------- prep: one block per probe b, one thread per f ----------
__global__ __launch_bounds__(64)
void prep_kernel(const float* __restrict__ probes,
                 const float* __restrict__ angles,
                 const float* __restrict__ qw,
                 const float* __restrict__ qmw) {
    __shared__ float red[2];
    const int b = blockIdx.x;   // 0..127
    const int f = threadIdx.x;  // 0..63
    const int warp = f >> 5;
    const int lane = f & 31;

    float x0 = probes[b * HD + f];
    float x1 = probes[b * HD + NF + f];
    float ss = fmaf(x0, x0, x1 * x1);
#pragma unroll
    for (int o = 16; o; o >>= 1) ss += __shfl_xor_sync(0xffffffffu, ss, o);
    if (lane == 0) red[warp] = ss;
    __syncthreads();
    float inv = 1.0f / (sqrtf(red[0] + red[1]) + EPSF);

    float pr = x0 * inv;
    float pi = x1 * inv;
    float c, s;
    sincosf(angles[f], &s, &c);
    float Pr = pr * c - pi * s;
    float Pi = pr * s + pi * c;
    float xw = qw[b * NF + f];
    float sp = (xw > 20.0f) ? xw : log1pf(expf(xw));
    float w = -sp;
    float mw = qmw[b * NF + f];

    int p = b & 63;
    int hi = b >> 6;
    g_probeA[(f * 64 + p) * 4 + 0 + hi] = Pr;
    g_probeA[(f * 64 + p) * 4 + 2 + hi] = Pi;
    g_probeW[(f * 64 + p) * 2 + hi]  = w;
    g_probeMW[(f * 64 + p) * 2 + hi] = mw;
}

// ---------- SMEM layout (float offsets) ----------
#define OFF_SA  0        // probeA: 16384 floats (64KB)
#define OFF_SW  16384    // probeW: 8192 floats (32KB)
#define OFF_QTA 24576    // q-table: 12 pairs * 9q * 64f * 4 fl = 27648 fl (108KB)
                         //   entry (pre-dup): {-qr, -qr, -qi, -qi}
#define SMEM_FLOATS 52224 // 208896 bytes

// Distance-only f-loop over JN q's. Warp handles 32 b-pairs (p = lane+32h).
template<int JN>
__device__ __forceinline__ void run_batch(uint32_t aP, uint32_t aW, uint32_t aQTA,
                                          u64 biasp, u64 EPS2,
                                          float* __restrict__ out, int q0, int p) {
    u64 acc[JN];
#pragma unroll
    for (int j = 0; j < JN; j++) acc[j] = biasp;

#pragma unroll 2
    for (int f = 0; f < NF; f++) {
        u64 Pr, Pi, w;
        asm("ld.shared.v2.b64 {%0,%1}, [%2];"
            : "=l"(Pr), "=l"(Pi) : "r"(aP + (uint32_t)f * 1024u));
        asm("ld.shared.b64 %0, [%1];"
            : "=l"(w) : "r"(aW + (uint32_t)f * 512u));

#pragma unroll
        for (int j = 0; j < JN; j++) {
            u64 nqr, nqi;   // pre-duplicated, broadcast load
            asm("ld.shared.v2.b64 {%0,%1}, [%2];"
                : "=l"(nqr), "=l"(nqi)
                : "r"(aQTA + ((uint32_t)j * 64u + (uint32_t)f) * 16u));

            u64 er = f2add(Pr, nqr);             // P - Q (q pre-negated)
            u64 ei = f2add(Pi, nqi);
            u64 d2 = f2fma(er, er, f2fma(ei, ei, EPS2));
            float lo, hi; f2upk(lo, hi, d2);
            u64 dist = f2pk(sqrt_apx(lo), sqrt_apx(hi));
            acc[j] = f2fma(dist, w, acc[j]);
        }
    }

#pragma unroll
    for (int j = 0; j < JN; j++) {
        float o0, o1; f2upk(o0, o1, acc[j]);
        float* orow = out + (size_t)(q0 + j) * NB;
        orow[p]      = o0;
        orow[p + 64] = o1;
    }
}

__global__ __launch_bounds__(THREADS, 1)
void main_kernel(const float* __restrict__ Q,
                 const float* __restrict__ bias,
                 float* __restrict__ out) {
    extern __shared__ float sm[];
    const int tid  = threadIdx.x;
    const int warp = tid >> 5;
    const int lane = tid & 31;
    const int pid  = warp >> 1;     // pair id 0..11
    const int h    = warp & 1;
    const int p    = lane + 32 * h; // b-pair index 0..63

    // Stage probe tables into SMEM
    {
        const float4* gA = (const float4*)g_probeA;
        const float4* gW = (const float4*)g_probeW;
        float4* sA4 = (float4*)(sm + OFF_SA);
        float4* sW4 = (float4*)(sm + OFF_SW);
        for (int i = tid; i < 4096; i += THREADS) sA4[i] = gA[i];
        for (int i = tid; i < 2048; i += THREADS) sW4[i] = gW[i];
    }

    const u64 biasp = f2pk(bias[p], bias[p + 64]);
    const u64 EPS2  = f2pk(EPSF, EPSF);

    __syncthreads();

    const uint32_t sbase = su32(sm);
    const uint32_t aP   = sbase + (uint32_t)p * 16u;
    const uint32_t aW   = sbase + (uint32_t)OFF_SW * 4u + (uint32_t)p * 8u;
    const uint32_t aQTA = sbase + ((uint32_t)OFF_QTA + (uint32_t)pid * (MAXQ * 64 * 4)) * 4u;
    float4* qta = (float4*)(sm + OFF_QTA + pid * MAXQ * 64 * 4);

    // ---- balanced contiguous q-range per warp-pair: 9 or 8 q, ONE batch ----
    const int npairs = gridDim.x * PAIRS_PER_CTA;
    const int gp = blockIdx.x * PAIRS_PER_CTA + pid;
    const int per = NQ / npairs;
    const int rem = NQ % npairs;
    int cnt, q0;
    if (gp < rem) { cnt = per + 1; q0 = gp * (per + 1); }
    else          { cnt = per;     q0 = rem * (per + 1) + (gp - rem) * per; }

    while (cnt > 0) {
        const int jn = (cnt > MAXQ) ? MAXQ : cnt;

        // batch prep: warps of the pair split q's by parity; strided loads
        for (int j = h; j < jn; j += 2) {
            const float* Qr = Q + (size_t)(q0 + j) * HD;
            float e0 = Qr[lane];
            float e1 = Qr[lane + 32];
            float e2 = Qr[lane + 64];
            float e3 = Qr[lane + 96];
            float ss = fmaf(e0, e0, fmaf(e1, e1, fmaf(e2, e2, e3 * e3)));
#pragma unroll
            for (int o = 16; o; o >>= 1) ss += __shfl_xor_sync(0xffffffffu, ss, o);
            float inv = rcp_apx(sqrt_apx(ss) + EPSF);
            float qr0 = e0 * inv, qr1 = e1 * inv;
            float qi0 = e2 * inv, qi1 = e3 * inv;
            qta[j * 64 + lane]      = make_float4(-qr0, -qr0, -qi0, -qi0);
            qta[j * 64 + lane + 32] = make_float4(-qr1, -qr1, -qi1, -qi1);
        }
        asm volatile("bar.sync %0, %1;" :: "r"(pid + 1), "r"(64) : "memory");

        switch (jn) {
            case 9:  run_batch<9>(aP, aW, aQTA, biasp, EPS2, out, q0, p); break;
            case 8:  run_batch<8>(aP, aW, aQTA, biasp, EPS2, out, q0, p); break;
            case 7:  run_batch<7>(aP, aW, aQTA, biasp, EPS2, out, q0, p); break;
            case 6:  run_batch<6>(aP, aW, aQTA, biasp, EPS2, out, q0, p); break;
            case 5:  run_batch<5>(aP, aW, aQTA, biasp, EPS2, out, q0, p); break;
            case 4:  run_batch<4>(aP, aW, aQTA, biasp, EPS2, out, q0, p); break;
            case 3:  run_batch<3>(aP, aW, aQTA, biasp, EPS2, out, q0, p); break;
            case 2:  run_batch<2>(aP, aW, aQTA, biasp, EPS2, out, q0, p); break;
            default: run_batch<1>(aP, aW, aQTA, biasp, EPS2, out, q0, p); break;
        }

        asm volatile("bar.sync %0, %1;" :: "r"(pid + 1), "r"(64) : "memory");
        q0 += jn;
        cnt -= jn;
    }
}

// ---------- epilogue: out[q][b] += sum_f qm[q,f] * mw[b,f] ----------
#define EPI_THREADS 256
__global__ __launch_bounds__(EPI_THREADS)
void epi_kernel(const float* __restrict__ Q, float* __restrict__ out) {
    __shared__ float smw[NF * 64 * 2];   // 32KB, packed {mw_p, mw_p+64}
    __shared__ float sqm[8][4 * 64];     // per-warp: 4 q x 64 f
    const int tid  = threadIdx.x;
    const int warp = tid >> 5;
    const int lane = tid & 31;

    for (int i = tid; i < NF * 64 * 2 / 4; i += EPI_THREADS)
        ((float4*)smw)[i] = ((const float4*)g_probeMW)[i];
    __syncthreads();

    const uint32_t aMW = su32(smw) + (uint32_t)lane * 8u;
    float* qmw_row = sqm[warp];
    const int q0 = blockIdx.x * 32 + warp * 4;

    // compute qm for 4 q's
#pragma unroll
    for (int i = 0; i < 4; i++) {
        const float* Qr = Q + (size_t)(q0 + i) * HD;
        float e0 = Qr[lane];
        float e1 = Qr[lane + 32];
        float e2 = Qr[lane + 64];
        float e3 = Qr[lane + 96];
        float ss = fmaf(e0, e0, fmaf(e1, e1, fmaf(e2, e2, e3 * e3)));
#pragma unroll
        for (int o = 16; o; o >>= 1) ss += __shfl_xor_sync(0xffffffffu, ss, o);
        float inv = rcp_apx(sqrt_apx(ss) + EPSF);
        float qr0 = e0 * inv, qr1 = e1 * inv;
        float qi0 = e2 * inv, qi1 = e3 * inv;
        qmw_row[i * 64 + lane]      = sqrt_apx(fmaf(qr0, qr0, fmaf(qi0, qi0, EPSF)));
        qmw_row[i * 64 + lane + 32] = sqrt_apx(fmaf(qr1, qr1, fmaf(qi1, qi1, EPSF)));
    }
    __syncwarp();

    // batched dot: 4 q x 2 b-pairs per lane (p = lane, lane+32)
    u64 acc0[4] = {0, 0, 0, 0}, acc1[4] = {0, 0, 0, 0};
#pragma unroll 4
    for (int f = 0; f < NF; f++) {
        u64 mw0, mw1;
        asm("ld.shared.b64 %0, [%1];" : "=l"(mw0) : "r"(aMW + (uint32_t)f * 512u));
        asm("ld.shared.b64 %0, [%1];" : "=l"(mw1) : "r"(aMW + (uint32_t)f * 512u + 256u));
#pragma unroll
        for (int i = 0; i < 4; i++) {
            float qm = qmw_row[i * 64 + f];
            u64 qm2 = f2pk(qm, qm);
            acc0[i] = f2fma(qm2, mw0, acc0[i]);
            acc1[i] = f2fma(qm2, mw1, acc1[i]);
        }
    }

#pragma unroll
    for (int i = 0; i < 4; i++) {
        float a0, a1, b0, b1;
        f2upk(a0, a1, acc0[i]);
        f2upk(b0, b1, acc1[i]);
        float* orow = out + (size_t)(q0 + i) * NB;
        orow[lane]      += a0;
        orow[lane + 64] += a1;
        orow[lane + 32] += b0;
        orow[lane + 96] += b1;
    }
}

extern "C" void kernel_launch(void* const* d_in, const int* in_sizes, int n_in,
                              void* d_out, int out_size) {
    const float* Q      = (const float*)d_in[0];
    const float* angles = (const float*)d_in[1];
    const float* probes = (const float*)d_in[2];
    const float* qw     = (const float*)d_in[3];
    const float* qmw    = (const float*)d_in[4];
    const float* qbias  = (const float*)d_in[5];
    float* out = (float*)d_out;

    static_assert(OFF_SW  == OFF_SA + NF * 64 * 4, "probeA region");
    static_assert(OFF_QTA == OFF_SW + NF * 64 * 2, "probeW region");
    static_assert(SMEM_FLOATS == OFF_QTA + PAIRS_PER_CTA * MAXQ * 64 * 4, "qta region");
    static_assert(SMEM_FLOATS * sizeof(float) <= 232448, "smem cap");

    cudaFuncSetAttribute(main_kernel,
                         cudaFuncAttributeMaxDynamicSharedMemorySize,
                         SMEM_FLOATS * (int)sizeof(float));

    int sms = 148;
    cudaDeviceGetAttribute(&sms, cudaDevAttrMultiProcessorCount, 0);

    prep_kernel<<<NB, 64>>>(probes, angles, qw, qmw);
    main_kernel<<<sms, THREADS, SMEM_FLOATS * sizeof(float)>>>(Q, qbias, out);
    epi_kernel<<<NQ / 32, EPI_THREADS>>>(Q, out);
}

// round 15
// speedup vs baseline: 1.0734x; 1.0734x over previous
#include <cuda_runtime.h>
#include <cstdint>

typedef unsigned long long u64;

#define NQ 16384
#define NB 128
#define NF 64
#define HD 128
#define EPSF 1e-8f

#define THREADS 768
#define WARPS_PER_CTA 24
#define PAIRS_PER_CTA 12
#define MAXQ 6

// prep outputs. Pair p couples b=p and b=p+64.
// g_probeA[(f*64+p)*4]  = {P_real[p], P_real[p+64], P_imag[p], P_imag[p+64]}
// g_probeW[(f*64+p)*2]  = {w_p,  w_p+64}
// g_probeMW[(f*64+p)*2] = {mw_p, mw_p+64}
__device__ float g_probeA[NF * 64 * 4];
__device__ float g_probeW[NF * 64 * 2];
__device__ float g_probeMW[NF * 64 * 2];

// ---------- f32x2 helpers ----------
__device__ __forceinline__ u64 f2pk(float lo, float hi) {
    u64 r; asm("mov.b64 %0, {%1,%2};" : "=l"(r) : "f"(lo), "f"(hi)); return r;
}
__device__ __forceinline__ void f2upk(float& lo, float& hi, u64 v) {
    asm("mov.b64 {%0,%1}, %2;" : "=f"(lo), "=f"(hi) : "l"(v));
}
__device__ __forceinline__ u64 f2add(u64 a, u64 b) {
    u64 d; asm("add.rn.f32x2 %0, %1, %2;" : "=l"(d) : "l"(a), "l"(b)); return d;
}
__device__ __forceinline__ u64 f2fma(u64 a, u64 b, u64 c) {
    u64 d; asm("fma.rn.f32x2 %0, %1, %2, %3;" : "=l"(d) : "l"(a), "l"(b), "l"(c)); return d;
}
__device__ __forceinline__ float sqrt_apx(float x) {
    float r; asm("sqrt.approx.f32 %0, %1;" : "=f"(r) : "f"(x)); return r;
}
__device__ __forceinline__ float rcp_apx(float x) {
    float r; asm("rcp.approx.f32 %0, %1;" : "=f"(r) : "f"(x)); return r;
}
__device__ __forceinline__ uint32_t su32(const void* p) {
    uint32_t a;
    asm("{ .reg .u64 t; cvta.to.shared.u64 t, %1; cvt.u32.u64 %0, t; }"
        : "=r"(a) : "l"(p));
    return a;
}

// ---------- prep: one block per probe b, one thread per f ----------
__global__ __launch_bounds__(64)
void prep_kernel(const float* __restrict__ probes,
                 const float* __restrict__ angles,
                 const float* __restrict__ qw,
                 const float* __restrict__ qmw) {
    __shared__ float red[2];
    const int b = blockIdx.x;   // 0..127
    const int f = threadIdx.x;  // 0..63
    const int warp = f >> 5;
    const int lane = f & 31;

    float x0 = probes[b * HD + f];
    float x1 = probes[b * HD + NF + f];
    float ss = fmaf(x0, x0, x1 * x1);
#pragma unroll
    for (int o = 16; o; o >>= 1) ss += __shfl_xor_sync(0xffffffffu, ss, o);
    if (lane == 0) red[warp] = ss;
    __syncthreads();
    float inv = 1.0f / (sqrtf(red[0] + red[1]) + EPSF);

    float pr = x0 * inv;
    float pi = x1 * inv;
    float c, s;
    sincosf(angles[f], &s, &c);
    float Pr = pr * c - pi * s;
    float Pi = pr * s + pi * c;
    float xw = qw[b * NF + f];
    float sp = (xw > 20.0f) ? xw : log1pf(expf(xw));
    float w = -sp;
    float mw = qmw[b * NF + f];

    int p = b & 63;
    int hi = b >> 6;
    g_probeA[(f * 64 + p) * 4 + 0 + hi] = Pr;
    g_probeA[(f * 64 + p) * 4 + 2 + hi] = Pi;
    g_probeW[(f * 64 + p) * 2 + hi]  = w;
    g_probeMW[(f * 64 + p) * 2 + hi] = mw;
}

// ---------- SMEM layout (float offsets) ----------
#define OFF_SA  0        // probeA: 16384 floats (64KB)
#define OFF_SW  16384    // probeW: 8192 floats (32KB)
#define OFF_SMW 24576    // probeMW: 8192 floats (32KB)
#define OFF_QTA 32768    // pre-dup q-table: 12 pairs * 6q * 64f * 4 fl = 18432 fl (72KB)
                         //   entry: {-qr, -qr, -qi, -qi}
#define OFF_QTM 51200    // qm scalars: 12 * 6 * 64 = 4608 fl (18KB)
#define SMEM_FLOATS 55808 // 223232 bytes

// Batch of JN q's. Warp handles 32 b-pairs (p = lane + 32*h).
// Phase 1: MUFU-paced distance loop (9 instr per (j,f)).
// Phase 2: magnitude-term dot (FMA/LSU only), then single store.
template<int JN>
__device__ __forceinline__ void run_batch(uint32_t aP, uint32_t aW, uint32_t aMW,
                                          uint32_t aQTA, uint32_t aQTM,
                                          u64 biasp, u64 EPS2,
                                          float* __restrict__ out, int q0, int p) {
    u64 acc[JN];
#pragma unroll
    for (int j = 0; j < JN; j++) acc[j] = biasp;

    // ---- phase 1: distances ----
#pragma unroll 2
    for (int f = 0; f < NF; f++) {
        u64 Pr, Pi, w;
        asm("ld.shared.v2.b64 {%0,%1}, [%2];"
            : "=l"(Pr), "=l"(Pi) : "r"(aP + (uint32_t)f * 1024u));
        asm("ld.shared.b64 %0, [%1];"
            : "=l"(w) : "r"(aW + (uint32_t)f * 512u));

#pragma unroll
        for (int j = 0; j < JN; j++) {
            u64 nqr, nqi;   // pre-duplicated, single broadcast load
            asm("ld.shared.v2.b64 {%0,%1}, [%2];"
                : "=l"(nqr), "=l"(nqi)
                : "r"(aQTA + ((uint32_t)j * 64u + (uint32_t)f) * 16u));

            u64 er = f2add(Pr, nqr);             // P - Q (q pre-negated)
            u64 ei = f2add(Pi, nqi);
            u64 d2 = f2fma(er, er, f2fma(ei, ei, EPS2));
            float lo, hi; f2upk(lo, hi, d2);
            u64 dist = f2pk(sqrt_apx(lo), sqrt_apx(hi));
            acc[j] = f2fma(dist, w, acc[j]);
        }
    }

    // ---- phase 2: magnitude term ----
#pragma unroll 4
    for (int f = 0; f < NF; f++) {
        u64 mw;
        asm("ld.shared.b64 %0, [%1];"
            : "=l"(mw) : "r"(aMW + (uint32_t)f * 512u));
#pragma unroll
        for (int j = 0; j < JN; j++) {
            float qm;
            asm("ld.shared.f32 %0, [%1];"
                : "=f"(qm) : "r"(aQTM + ((uint32_t)j * 64u + (uint32_t)f) * 4u));
            u64 qm2 = f2pk(qm, qm);
            acc[j] = f2fma(qm2, mw, acc[j]);
        }
    }

#pragma unroll
    for (int j = 0; j < JN; j++) {
        float o0, o1; f2upk(o0, o1, acc[j]);
        float* orow = out + (size_t)(q0 + j) * NB;
        orow[p]      = o0;
        orow[p + 64] = o1;
    }
}

__global__ __launch_bounds__(THREADS, 1)
void main_kernel(const float* __restrict__ Q,
                 const float* __restrict__ bias,
                 float* __restrict__ out) {
    extern __shared__ float sm[];
    const int tid  = threadIdx.x;
    const int warp = tid >> 5;
    const int lane = tid & 31;
    const int pid  = warp >> 1;     // pair id 0..11
    const int h    = warp & 1;
    const int p    = lane + 32 * h; // b-pair index 0..63

    // Stage probe tables into SMEM
    {
        const float4* gA  = (const float4*)g_probeA;
        const float4* gW  = (const float4*)g_probeW;
        const float4* gMW = (const float4*)g_probeMW;
        float4* sA4  = (float4*)(sm + OFF_SA);
        float4* sW4  = (float4*)(sm + OFF_SW);
        float4* sMW4 = (float4*)(sm + OFF_SMW);
        for (int i = tid; i < 4096; i += THREADS) sA4[i] = gA[i];
        for (int i = tid; i < 2048; i += THREADS) { sW4[i] = gW[i]; sMW4[i] = gMW[i]; }
    }

    const u64 biasp = f2pk(bias[p], bias[p + 64]);
    const u64 EPS2  = f2pk(EPSF, EPSF);

    __syncthreads();

    const uint32_t sbase = su32(sm);
    const uint32_t aP   = sbase + (uint32_t)p * 16u;
    const uint32_t aW   = sbase + (uint32_t)OFF_SW  * 4u + (uint32_t)p * 8u;
    const uint32_t aMW  = sbase + (uint32_t)OFF_SMW * 4u + (uint32_t)p * 8u;
    const uint32_t aQTA = sbase + ((uint32_t)OFF_QTA + (uint32_t)pid * (MAXQ * 64 * 4)) * 4u;
    const uint32_t aQTM = sbase + ((uint32_t)OFF_QTM + (uint32_t)pid * (MAXQ * 64)) * 4u;
    float4* qta = (float4*)(sm + OFF_QTA + pid * MAXQ * 64 * 4);
    float*  qtm = sm + OFF_QTM + pid * MAXQ * 64;

    // ---- balanced contiguous q-range per warp-pair (9 or 8 q) ----
    const int npairs = gridDim.x * PAIRS_PER_CTA;
    const int gp = blockIdx.x * PAIRS_PER_CTA + pid;
    const int per = NQ / npairs;
    const int rem = NQ % npairs;
    int cnt, q0;
    if (gp < rem) { cnt = per + 1; q0 = gp * (per + 1); }
    else          { cnt = per;     q0 = rem * (per + 1) + (gp - rem) * per; }

    while (cnt > 0) {
        const int jn = (cnt > MAXQ) ? MAXQ : cnt;

        // batch prep: warps of the pair split q's by parity; strided loads
        for (int j = h; j < jn; j += 2) {
            const float* Qr = Q + (size_t)(q0 + j) * HD;
            float e0 = Qr[lane];
            float e1 = Qr[lane + 32];
            float e2 = Qr[lane + 64];
            float e3 = Qr[lane + 96];
            float ss = fmaf(e0, e0, fmaf(e1, e1, fmaf(e2, e2, e3 * e3)));
#pragma unroll
            for (int o = 16; o; o >>= 1) ss += __shfl_xor_sync(0xffffffffu, ss, o);
            float inv = rcp_apx(sqrt_apx(ss) + EPSF);
            float qr0 = e0 * inv, qr1 = e1 * inv;
            float qi0 = e2 * inv, qi1 = e3 * inv;
            qta[j * 64 + lane]      = make_float4(-qr0, -qr0, -qi0, -qi0);
            qta[j * 64 + lane + 32] = make_float4(-qr1, -qr1, -qi1, -qi1);
            qtm[j * 64 + lane]      = sqrt_apx(fmaf(qr0, qr0, fmaf(qi0, qi0, EPSF)));
            qtm[j * 64 + lane + 32] = sqrt_apx(fmaf(qr1, qr1, fmaf(qi1, qi1, EPSF)));
        }
        asm volatile("bar.sync %0, %1;" :: "r"(pid + 1), "r"(64) : "memory");

        switch (jn) {
            case 6:  run_batch<6>(aP, aW, aMW, aQTA, aQTM, biasp, EPS2, out, q0, p); break;
            case 5:  run_batch<5>(aP, aW, aMW, aQTA, aQTM, biasp, EPS2, out, q0, p); break;
            case 4:  run_batch<4>(aP, aW, aMW, aQTA, aQTM, biasp, EPS2, out, q0, p); break;
            case 3:  run_batch<3>(aP, aW, aMW, aQTA, aQTM, biasp, EPS2, out, q0, p); break;
            case 2:  run_batch<2>(aP, aW, aMW, aQTA, aQTM, biasp, EPS2, out, q0, p); break;
            default: run_batch<1>(aP, aW, aMW, aQTA, aQTM, biasp, EPS2, out, q0, p); break;
        }

        asm volatile("bar.sync %0, %1;" :: "r"(pid + 1), "r"(64) : "memory");
        q0 += jn;
        cnt -= jn;
    }
}

extern "C" void kernel_launch(void* const* d_in, const int* in_sizes, int n_in,
                              void* d_out, int out_size) {
    const float* Q      = (const float*)d_in[0];
    const float* angles = (const float*)d_in[1];
    const float* probes = (const float*)d_in[2];
    const float* qw     = (const float*)d_in[3];
    const float* qmw    = (const float*)d_in[4];
    const float* qbias  = (const float*)d_in[5];
    float* out = (float*)d_out;

    static_assert(OFF_SW  == OFF_SA + NF * 64 * 4, "probeA region");
    static_assert(OFF_SMW == OFF_SW + NF * 64 * 2, "probeW region");
    static_assert(OFF_QTA == OFF_SMW + NF * 64 * 2, "probeMW region");
    static_assert(OFF_QTM == OFF_QTA + PAIRS_PER_CTA * MAXQ * 64 * 4, "qta region");
    static_assert(SMEM_FLOATS == OFF_QTM + PAIRS_PER_CTA * MAXQ * 64, "qtm region");
    static_assert(SMEM_FLOATS * sizeof(float) <= 232448, "smem cap");

    cudaFuncSetAttribute(main_kernel,
                         cudaFuncAttributeMaxDynamicSharedMemorySize,
                         SMEM_FLOATS * (int)sizeof(float));

    int sms = 148;
    cudaDeviceGetAttribute(&sms, cudaDevAttrMultiProcessorCount, 0);

    prep_kernel<<<NB, 64>>>(probes, angles, qw, qmw);
    main_kernel<<<sms, THREADS, SMEM_FLOATS * sizeof(float)>>>(Q, qbias, out);
}

// round 16
// speedup vs baseline: 1.2062x; 1.1237x over previous
#include <cuda_runtime.h>
#include <cstdint>

typedef unsigned long long u64;

#define NQ 16384
#define NB 128
#define NF 64
#define HD 128
#define EPSF 1e-8f

#define THREADS 768
#define WARPS_PER_CTA 24
#define PAIRS_PER_CTA 12
#define MAXQ 5

// Packed probe tables (prep output). Pair p couples b=p and b=p+64.
// g_probeA[f][p] = {P_real[p], P_real[p+64], P_imag[p], P_imag[p+64]}
// g_probeB[f][p] = {w[p],      w[p+64],      mw[p],     mw[p+64]}
__device__ float g_probeA[NF * 64 * 4];
__device__ float g_probeB[NF * 64 * 4];

// ---------- f32x2 helpers ----------
__device__ __forceinline__ u64 f2pk(float lo, float hi) {
    u64 r; asm("mov.b64 %0, {%1,%2};" : "=l"(r) : "f"(lo), "f"(hi)); return r;
}
__device__ __forceinline__ void f2upk(float& lo, float& hi, u64 v) {
    asm("mov.b64 {%0,%1}, %2;" : "=f"(lo), "=f"(hi) : "l"(v));
}
__device__ __forceinline__ u64 f2add(u64 a, u64 b) {
    u64 d; asm("add.rn.f32x2 %0, %1, %2;" : "=l"(d) : "l"(a), "l"(b)); return d;
}
__device__ __forceinline__ u64 f2fma(u64 a, u64 b, u64 c) {
    u64 d; asm("fma.rn.f32x2 %0, %1, %2, %3;" : "=l"(d) : "l"(a), "l"(b), "l"(c)); return d;
}
__device__ __forceinline__ float sqrt_apx(float x) {
    float r; asm("sqrt.approx.f32 %0, %1;" : "=f"(r) : "f"(x)); return r;
}
__device__ __forceinline__ float rcp_apx(float x) {
    float r; asm("rcp.approx.f32 %0, %1;" : "=f"(r) : "f"(x)); return r;
}
__device__ __forceinline__ uint32_t su32(const void* p) {
    uint32_t a;
    asm("{ .reg .u64 t; cvta.to.shared.u64 t, %1; cvt.u32.u64 %0, t; }"
        : "=r"(a) : "l"(p));
    return a;
}

// ---------- prep: one block per probe b, one thread per f ----------
// Fast-math transcendentals: the prep kernel was a 5.3us latency tail at
// occ 3%; __sincosf/__expf/__logf cut the serial chain ~3x. Accuracy is
// ~1e-5 rel, far inside the 1e-3 budget.
__global__ __launch_bounds__(64)
void prep_kernel(const float* __restrict__ probes,
                 const float* __restrict__ angles,
                 const float* __restrict__ qw,
                 const float* __restrict__ qmw) {
    __shared__ float red[2];
    const int b = blockIdx.x;   // 0..127
    const int f = threadIdx.x;  // 0..63
    const int warp = f >> 5;
    const int lane = f & 31;

    float x0 = probes[b * HD + f];
    float x1 = probes[b * HD + NF + f];
    float ss = fmaf(x0, x0, x1 * x1);
#pragma unroll
    for (int o = 16; o; o >>= 1) ss += __shfl_xor_sync(0xffffffffu, ss, o);
    if (lane == 0) red[warp] = ss;
    __syncthreads();
    float inv = 1.0f / (sqrtf(red[0] + red[1]) + EPSF);

    float pr = x0 * inv;
    float pi = x1 * inv;
    float c, s;
    __sincosf(angles[f], &s, &c);
    float Pr = pr * c - pi * s;
    float Pi = pr * s + pi * c;
    float xw = qw[b * NF + f];
    // softplus(x) = max(x,0) + log(1 + exp(-|x|)), fast-math variants
    float sp = fmaxf(xw, 0.0f) + __logf(1.0f + __expf(-fabsf(xw)));
    float w = -sp;
    float mw = qmw[b * NF + f];

    int p = b & 63;
    int hi = b >> 6;
    int base = (f * 64 + p) * 4;
    g_probeA[base + 0 + hi] = Pr;
    g_probeA[base + 2 + hi] = Pi;
    g_probeB[base + 0 + hi] = w;
    g_probeB[base + 2 + hi] = mw;
}

// ---------- SMEM layout (float offsets) ----------
#define OFF_SA  0                           // probeA: 16384 floats (64KB)
#define OFF_SB  16384                       // probeB: 16384 floats (64KB)
#define OFF_QT  32768                       // q-tables: 12 pairs * 5q * 64f * 4 = 15360 floats (60KB)
#define OFF_QN  48128                       // per-warp qn scratch: 24*128 = 3072 floats (12KB)
#define SMEM_FLOATS 51200                   // 200 KB

// f-loop over a batch of JN q's. Warp handles 32 b-pairs (p = lane + 32*h).
template<int JN>
__device__ __forceinline__ void run_batch(uint32_t aA0, uint32_t aB0, uint32_t aQT,
                                          u64 biasp, u64 EPS2,
                                          float* __restrict__ out, int q0, int p) {
    u64 acc[JN];
#pragma unroll
    for (int j = 0; j < JN; j++) acc[j] = biasp;

#pragma unroll 2
    for (int f = 0; f < NF; f++) {
        const uint32_t fo = (uint32_t)f * 1024u;
        u64 Pr, Pi, w, mw;
        asm("ld.shared.v2.b64 {%0,%1}, [%2];" : "=l"(Pr), "=l"(Pi) : "r"(aA0 + fo));
        asm("ld.shared.v2.b64 {%0,%1}, [%2];" : "=l"(w),  "=l"(mw) : "r"(aB0 + fo));

        float tx[JN], ty[JN], tz[JN], tw_[JN];
#pragma unroll
        for (int j = 0; j < JN; j++) {
            asm("ld.shared.v4.f32 {%0,%1,%2,%3}, [%4];"
                : "=f"(tx[j]), "=f"(ty[j]), "=f"(tz[j]), "=f"(tw_[j])
                : "r"(aQT + (uint32_t)j * 1024u + (uint32_t)f * 16u));
        }

#pragma unroll
        for (int j = 0; j < JN; j++) {
            u64 nqr = f2pk(tx[j], tx[j]);
            u64 nqi = f2pk(ty[j], ty[j]);
            u64 qm2 = f2pk(tz[j], tz[j]);
            u64 er = f2add(Pr, nqr);
            u64 ei = f2add(Pi, nqi);
            u64 d2 = f2fma(er, er, f2fma(ei, ei, EPS2));
            float lo, hi; f2upk(lo, hi, d2);
            u64 dist = f2pk(sqrt_apx(lo), sqrt_apx(hi));
            acc[j] = f2fma(dist, w, acc[j]);
            acc[j] = f2fma(qm2, mw, acc[j]);
        }
    }

#pragma unroll
    for (int j = 0; j < JN; j++) {
        float o0, o1; f2upk(o0, o1, acc[j]);
        float* orow = out + (size_t)(q0 + j) * NB;
        orow[p]      = o0;
        orow[p + 64] = o1;
    }
}

__global__ __launch_bounds__(THREADS, 1)
void main_kernel(const float* __restrict__ Q,
                 const float* __restrict__ bias,
                 float* __restrict__ out) {
    extern __shared__ float sm[];
    const int tid  = threadIdx.x;
    const int warp = tid >> 5;
    const int lane = tid & 31;
    const int pid  = warp >> 1;     // pair id 0..11
    const int h    = warp & 1;      // warp half within pair
    const int p    = lane + 32 * h; // b-pair index 0..63

    // Stage probe tables into SMEM
    {
        const float4* gA = (const float4*)g_probeA;
        const float4* gB = (const float4*)g_probeB;
        float4* sA4 = (float4*)(sm + OFF_SA);
        float4* sB4 = (float4*)(sm + OFF_SB);
        for (int i = tid; i < NF * 64; i += THREADS) {
            sA4[i] = gA[i];
            sB4[i] = gB[i];
        }
    }

    const u64 biasp = f2pk(bias[p], bias[p + 64]);
    const u64 EPS2  = f2pk(EPSF, EPSF);

    __syncthreads();

    const uint32_t sbase = su32(sm);
    const uint32_t aA0 = sbase + (uint32_t)p * 16u;
    const uint32_t aB0 = sbase + (uint32_t)OFF_SB * 4u + (uint32_t)p * 16u;
    const uint32_t aQT = sbase + (uint32_t)OFF_QT * 4u + (uint32_t)pid * (MAXQ * 64u * 16u);
    float*  qn = sm + OFF_QN + warp * 128;
    float4* qt = (float4*)(sm + OFF_QT + pid * MAXQ * 64 * 4);

    // ---- contiguous q-range assignment per warp-pair (balanced to +/-1 q) ----
    const int npairs = gridDim.x * PAIRS_PER_CTA;
    const int gp = blockIdx.x * PAIRS_PER_CTA + pid;
    const int per = NQ / npairs;
    const int rem = NQ % npairs;
    int cnt, q0;
    if (gp < rem) { cnt = per + 1; q0 = gp * (per + 1); }
    else          { cnt = per;     q0 = rem * (per + 1) + (gp - rem) * per; }

    while (cnt > 0) {
        const int jn = (cnt > MAXQ) ? MAXQ : cnt;   // 9 -> 5+4, 8 -> 5+3

        // ---- batch prep: warps of the pair split the q's by parity of j ----
        for (int j = h; j < jn; j += 2) {
            const float4* Qv = (const float4*)(Q + (size_t)(q0 + j) * HD);
            float4 v = Qv[lane];
            float ss = fmaf(v.x, v.x, fmaf(v.y, v.y, fmaf(v.z, v.z, v.w * v.w)));
#pragma unroll
            for (int o = 16; o; o >>= 1) ss += __shfl_xor_sync(0xffffffffu, ss, o);
            float inv = rcp_apx(sqrt_apx(ss) + EPSF);
            ((float4*)qn)[lane] = make_float4(v.x * inv, v.y * inv, v.z * inv, v.w * inv);
            __syncwarp();
#pragma unroll
            for (int k = 0; k < 2; k++) {
                int f = lane + k * 32;
                float qr = qn[f];
                float qi = qn[f + 64];
                float qm = sqrt_apx(fmaf(qr, qr, fmaf(qi, qi, EPSF)));
                qt[j * 64 + f] = make_float4(-qr, -qi, qm, 0.0f);
            }
            __syncwarp();
        }
        // pair-scoped named barrier (ids 1..12; 0 reserved for __syncthreads)
        asm volatile("bar.sync %0, %1;" :: "r"(pid + 1), "r"(64) : "memory");

        switch (jn) {
            case 5: run_batch<5>(aA0, aB0, aQT, biasp, EPS2, out, q0, p); break;
            case 4: run_batch<4>(aA0, aB0, aQT, biasp, EPS2, out, q0, p); break;
            case 3: run_batch<3>(aA0, aB0, aQT, biasp, EPS2, out, q0, p); break;
            case 2: run_batch<2>(aA0, aB0, aQT, biasp, EPS2, out, q0, p); break;
            default: run_batch<1>(aA0, aB0, aQT, biasp, EPS2, out, q0, p); break;
        }

        // protect qt against next batch's overwrite while partner still reads
        asm volatile("bar.sync %0, %1;" :: "r"(pid + 1), "r"(64) : "memory");

        q0 += jn;
        cnt -= jn;
    }
}

extern "C" void kernel_launch(void* const* d_in, const int* in_sizes, int n_in,
                              void* d_out, int out_size) {
    const float* Q      = (const float*)d_in[0];
    const float* angles = (const float*)d_in[1];
    const float* probes = (const float*)d_in[2];
    const float* qw     = (const float*)d_in[3];
    const float* qmw    = (const float*)d_in[4];
    const float* qbias  = (const float*)d_in[5];
    float* out = (float*)d_out;

    static_assert(SMEM_FLOATS * sizeof(float) == 204800, "smem layout");
    static_assert(OFF_QT + PAIRS_PER_CTA * MAXQ * 64 * 4 <= OFF_QN, "qt overlap");
    static_assert(OFF_QN + WARPS_PER_CTA * 128 <= SMEM_FLOATS, "qn overlap");

    cudaFuncSetAttribute(main_kernel,
                         cudaFuncAttributeMaxDynamicSharedMemorySize,
                         SMEM_FLOATS * (int)sizeof(float));

    int sms = 148;
    cudaDeviceGetAttribute(&sms, cudaDevAttrMultiProcessorCount, 0);

    prep_kernel<<<NB, 64>>>(probes, angles, qw, qmw);
    main_kernel<<<sms, THREADS, SMEM_FLOATS * sizeof(float)>>>(Q, qbias, out);
}